// round 13
// baseline (speedup 1.0000x reference)
#include <cuda_runtime.h>
#include <cuda_bf16.h>
#include <cstdint>

#define NN 100000
#define EE 1600000
#define IND 128
#define HID 64
#define MTILE 128
#define NBLK ((NN + MTILE - 1) / MTILE)
#define KCH 64
#define ROWP 68   // padded smem row length (bf16 elems) -> 136B

// scratch (static device globals; allocation-free)
__device__ float g_ft[NN * HID];
__device__ float g_res[NN * HID];
__device__ float g_sdst[NN];
__device__ float g_ssrc[NN];
__device__ int   g_rowptr[NN + 1];
__device__ float g_wl[HID];
__device__ float g_wr[HID];
// B operand [N=128][K=128]: n<64 = W_fc col n, n>=64 = W_res col n-64; hi/lo bf16 split
__device__ __nv_bfloat16 g_Bhi[128 * 128];
__device__ __nv_bfloat16 g_Blo[128 * 128];

// ---------------------------------------------------------------------------
#define MMA_BF16(c, a, b0, b1) \
    asm volatile("mma.sync.aligned.m16n8k16.row.col.f32.bf16.bf16.f32 " \
        "{%0,%1,%2,%3}, {%4,%5,%6,%7}, {%8,%9}, {%0,%1,%2,%3};" \
        : "+f"((c)[0]), "+f"((c)[1]), "+f"((c)[2]), "+f"((c)[3]) \
        : "r"((a)[0]), "r"((a)[1]), "r"((a)[2]), "r"((a)[3]), "r"(b0), "r"(b1))

// ---------------------------------------------------------------------------
// Blocks 0..127: build B operand (transposed, hi/lo bf16 split) B[n][k] = W[k][n].
// Block 128: wl[h] = sum_a W_l[h][a], wr likewise.
__global__ void k_prep(const float* __restrict__ Wfc, const float* __restrict__ Wres,
                       const float* __restrict__ Wl, const float* __restrict__ Wr) {
    if (blockIdx.x == 128) {
        int t = threadIdx.x;
        if (t < 64) {
            float sl = 0.f, sr = 0.f;
#pragma unroll
            for (int a = 0; a < 64; a++) { sl += Wl[t * 64 + a]; sr += Wr[t * 64 + a]; }
            g_wl[t] = sl; g_wr[t] = sr;
        }
        return;
    }
    int n = blockIdx.x;   // 0..127
    int k = threadIdx.x;  // 0..127
    float v = (n < 64) ? Wfc[k * 64 + n] : Wres[k * 64 + (n - 64)];
    __nv_bfloat16 h = __float2bfloat16(v);
    g_Bhi[n * 128 + k] = h;
    g_Blo[n * 128 + k] = __float2bfloat16(v - __bfloat162float(h));
}

// ---------------------------------------------------------------------------
// HMMA fused double GEMM with 3xbf16 split for fp32 accuracy.
// CTA: M=128 x N=128 ([ft|res]) x K=128 in two K=64 chunks. 256 threads = 8 warps.
#define AHI_OFF 0
#define ALO_OFF 17408
#define BHI_OFF 34816
#define BLO_OFF 52224
#define DYN_BYTES 69632
__global__ void __launch_bounds__(256) k_gemm_mma(const float* __restrict__ feats) {
    extern __shared__ __align__(16) char sm[];
    __shared__ float s_wl[64], s_wr[64];
    __nv_bfloat16* Ahi = (__nv_bfloat16*)(sm + AHI_OFF);
    __nv_bfloat16* Alo = (__nv_bfloat16*)(sm + ALO_OFF);
    __nv_bfloat16* Bhi = (__nv_bfloat16*)(sm + BHI_OFF);
    __nv_bfloat16* Blo = (__nv_bfloat16*)(sm + BLO_OFF);

    int tid = threadIdx.x;
    int wid = tid >> 5, lane = tid & 31;
    int g = lane >> 2, t = lane & 3;
    int warpM = wid >> 1, warpN = wid & 1;
    int mbase = warpM * 32, nbase = warpN * 64;
    if (tid < 64) { s_wl[tid] = g_wl[tid]; s_wr[tid] = g_wr[tid]; }

    int m0 = blockIdx.x * MTILE;
    int rowlim = NN - m0;

    float acc[2][8][4];
#pragma unroll
    for (int mt = 0; mt < 2; mt++)
#pragma unroll
        for (int nt = 0; nt < 8; nt++)
#pragma unroll
            for (int q = 0; q < 4; q++) acc[mt][nt][q] = 0.f;

    const uint2* bhig2 = (const uint2*)g_Bhi;  // row = 32 uint2
    const uint2* blog2 = (const uint2*)g_Blo;

    for (int kc = 0; kc < IND; kc += KCH) {
        // ---- A chunk: float4 loads (fp32 -> hi/lo bf16), stored as uint2 ----
#pragma unroll
        for (int i = 0; i < 8; i++) {
            int p = tid + i * 256;      // 0..2047
            int r = p >> 4;             // row 0..127
            int q = p & 15;             // float4 idx in 64-float chunk
            float4 v = (r < rowlim) ? *(const float4*)&feats[(size_t)(m0 + r) * IND + kc + 4 * q]
                                    : make_float4(0.f, 0.f, 0.f, 0.f);
            __nv_bfloat162 h01 = __floats2bfloat162_rn(v.x, v.y);
            __nv_bfloat162 h23 = __floats2bfloat162_rn(v.z, v.w);
            __nv_bfloat162 l01 = __floats2bfloat162_rn(v.x - __bfloat162float(h01.x),
                                                       v.y - __bfloat162float(h01.y));
            __nv_bfloat162 l23 = __floats2bfloat162_rn(v.z - __bfloat162float(h23.x),
                                                       v.w - __bfloat162float(h23.y));
            uint2 hh, ll;
            hh.x = *(uint32_t*)&h01; hh.y = *(uint32_t*)&h23;
            ll.x = *(uint32_t*)&l01; ll.y = *(uint32_t*)&l23;
            *(uint2*)&Ahi[r * ROWP + 4 * q] = hh;
            *(uint2*)&Alo[r * ROWP + 4 * q] = ll;
        }
        // ---- B chunk: uint2 loads (prebuilt bf16 hi/lo) ----
#pragma unroll
        for (int i = 0; i < 8; i++) {
            int p = tid + i * 256;      // 0..2047
            int r = p >> 4;             // row/n 0..127
            int q = p & 15;             // uint2 idx in 32-u32 chunk
            uint2 bh = bhig2[r * 32 + (kc >> 2) + q];
            uint2 bl = blog2[r * 32 + (kc >> 2) + q];
            *(uint2*)&Bhi[r * ROWP + 4 * q] = bh;
            *(uint2*)&Blo[r * ROWP + 4 * q] = bl;
        }
        __syncthreads();

        // ---- mma over 4 k-steps of 16 ----
#pragma unroll
        for (int ks = 0; ks < 4; ks++) {
            int k0 = ks * 16;
            uint32_t aH[2][4], aL[2][4];
#pragma unroll
            for (int mt = 0; mt < 2; mt++) {
                int row = mbase + mt * 16 + g;
                int base = row * ROWP + k0 + 2 * t;
                aH[mt][0] = *(const uint32_t*)&Ahi[base];
                aH[mt][1] = *(const uint32_t*)&Ahi[base + 8 * ROWP];
                aH[mt][2] = *(const uint32_t*)&Ahi[base + 8];
                aH[mt][3] = *(const uint32_t*)&Ahi[base + 8 * ROWP + 8];
                aL[mt][0] = *(const uint32_t*)&Alo[base];
                aL[mt][1] = *(const uint32_t*)&Alo[base + 8 * ROWP];
                aL[mt][2] = *(const uint32_t*)&Alo[base + 8];
                aL[mt][3] = *(const uint32_t*)&Alo[base + 8 * ROWP + 8];
            }
#pragma unroll
            for (int nt = 0; nt < 8; nt++) {
                int n = nbase + nt * 8 + g;
                int bb = n * ROWP + k0 + 2 * t;
                uint32_t bH0 = *(const uint32_t*)&Bhi[bb];
                uint32_t bH1 = *(const uint32_t*)&Bhi[bb + 8];
                uint32_t bL0 = *(const uint32_t*)&Blo[bb];
                uint32_t bL1 = *(const uint32_t*)&Blo[bb + 8];
#pragma unroll
                for (int mt = 0; mt < 2; mt++) {
                    MMA_BF16(acc[mt][nt], aH[mt], bH0, bH1);
                    MMA_BF16(acc[mt][nt], aL[mt], bH0, bH1);
                    MMA_BF16(acc[mt][nt], aH[mt], bL0, bL1);
                }
            }
        }
        __syncthreads();
    }

    // ---- sdst/ssrc from fragments (warps covering cols 0..63 = ft) ----
    if (warpN == 0) {
        float pl[2][2] = {}, pr[2][2] = {};
#pragma unroll
        for (int mt = 0; mt < 2; mt++)
#pragma unroll
            for (int nt = 0; nt < 8; nt++) {
                int col = nt * 8 + 2 * t;
                float wl0 = s_wl[col], wl1 = s_wl[col + 1];
                float wr0 = s_wr[col], wr1 = s_wr[col + 1];
                pl[mt][0] += acc[mt][nt][0] * wl0 + acc[mt][nt][1] * wl1;
                pl[mt][1] += acc[mt][nt][2] * wl0 + acc[mt][nt][3] * wl1;
                pr[mt][0] += acc[mt][nt][0] * wr0 + acc[mt][nt][1] * wr1;
                pr[mt][1] += acc[mt][nt][2] * wr0 + acc[mt][nt][3] * wr1;
            }
#pragma unroll
        for (int off = 1; off <= 2; off <<= 1) {
#pragma unroll
            for (int mt = 0; mt < 2; mt++)
#pragma unroll
                for (int h = 0; h < 2; h++) {
                    pl[mt][h] += __shfl_xor_sync(0xffffffffu, pl[mt][h], off);
                    pr[mt][h] += __shfl_xor_sync(0xffffffffu, pr[mt][h], off);
                }
        }
        if (t == 0) {
#pragma unroll
            for (int mt = 0; mt < 2; mt++)
#pragma unroll
                for (int h = 0; h < 2; h++) {
                    int m = m0 + mbase + mt * 16 + g + h * 8;
                    if (m < NN) { g_sdst[m] = pl[mt][h]; g_ssrc[m] = pr[mt][h]; }
                }
        }
    }

    // ---- stage C in smem, then coalesced copy-out ----
    float* stage = (float*)sm;  // [128][132]
#pragma unroll
    for (int mt = 0; mt < 2; mt++)
#pragma unroll
        for (int nt = 0; nt < 8; nt++) {
            int row = mbase + mt * 16 + g;
            int col = nbase + nt * 8 + 2 * t;
            *(float2*)&stage[row * 132 + col] = make_float2(acc[mt][nt][0], acc[mt][nt][1]);
            *(float2*)&stage[(row + 8) * 132 + col] = make_float2(acc[mt][nt][2], acc[mt][nt][3]);
        }
    __syncthreads();

#pragma unroll
    for (int i = 0; i < 8; i++) {
        int p = tid + i * 256;   // 0..2047
        int r = p >> 4, c4 = p & 15;
        if (r < rowlim) {
            *(float4*)&g_ft[(size_t)(m0 + r) * 64 + c4 * 4]  = *(float4*)&stage[r * 132 + c4 * 4];
            *(float4*)&g_res[(size_t)(m0 + r) * 64 + c4 * 4] = *(float4*)&stage[r * 132 + 64 + c4 * 4];
        }
    }
}

// ---------------------------------------------------------------------------
// CSR row pointers: one load per thread; prev from shfl_up (lane 0 reloads).
__global__ void k_rowptr(const int* __restrict__ dst) {
    int e = blockIdx.x * blockDim.x + threadIdx.x;
    int lane = threadIdx.x & 31;
    int cur = (e < EE) ? dst[e] : 0;
    int prev = __shfl_up_sync(0xffffffffu, cur, 1);
    if (lane == 0) prev = (e == 0) ? -1 : ((e < EE) ? dst[e - 1] : 0);
    if (e < EE) {
        for (int n = prev + 1; n <= cur; n++) g_rowptr[n] = e;
        if (e == EE - 1)
            for (int n = cur + 1; n <= NN; n++) g_rowptr[n] = EE;
    }
}

// ---------------------------------------------------------------------------
// One warp per destination node, single-pass online softmax.
// Gather: 2 edges/iteration — lanes 0-15 handle even edges, 16-31 odd edges;
// each half loads the full 64-float row as 16 x float4. Invalid lanes carry
// ex=0 / sr=0, so shuffling from lane p+half needs no clamping: a phantom
// edge contributes 0 through a safe address.
__global__ void __launch_bounds__(256) k_agg(const int* __restrict__ src, float* __restrict__ out) {
    int warp = (blockIdx.x * blockDim.x + threadIdx.x) >> 5;
    int lane = threadIdx.x & 31;
    if (warp >= NN) return;
    int half = lane >> 4;   // 0: even edges, 1: odd edges
    int hl = lane & 15;     // float4 slot within row

    int s0 = g_rowptr[warp];
    int s1 = g_rowptr[warp + 1];
    float sd = g_sdst[warp];

    float m = -3.402823e38f;
    float a0 = 0.f, a1 = 0.f, a2 = 0.f, a3 = 0.f, den = 0.f;
    const float4* __restrict__ ft4 = (const float4*)g_ft;

    for (int e0 = s0; e0 < s1; e0 += 32) {
        int e = e0 + lane;
        float s = -3.402823e38f;
        int sr = 0;
        if (e < s1) {
            sr = src[e];
            s = sd + g_ssrc[sr];
            s = s > 0.f ? s : 0.01f * s;
        }
        float cm = s;
#pragma unroll
        for (int o = 16; o > 0; o >>= 1) cm = fmaxf(cm, __shfl_xor_sync(0xffffffffu, cm, o));
        float newm = fmaxf(m, cm);
        float scale = expf(m - newm);   // first chunk: exp(-inf)=0, accs are 0 anyway
        a0 *= scale; a1 *= scale; a2 *= scale; a3 *= scale; den *= scale;
        m = newm;

        float ex = (e < s1) ? expf(s - m) : 0.f;
        den += ex;
        int cnt = min(32, s1 - e0);
#pragma unroll 2
        for (int p = 0; p < cnt; p += 2) {
            int idx = p + half;             // <= 31 always (p even, p < cnt <= 32)
            float exj = __shfl_sync(0xffffffffu, ex, idx);
            int srj = __shfl_sync(0xffffffffu, sr, idx);
            float4 v = ft4[srj * 16 + hl];
            a0 += exj * v.x; a1 += exj * v.y; a2 += exj * v.z; a3 += exj * v.w;
        }
    }
    // combine even/odd-edge halves (lane L and L+16 hold same columns)
    a0 += __shfl_xor_sync(0xffffffffu, a0, 16);
    a1 += __shfl_xor_sync(0xffffffffu, a1, 16);
    a2 += __shfl_xor_sync(0xffffffffu, a2, 16);
    a3 += __shfl_xor_sync(0xffffffffu, a3, 16);
#pragma unroll
    for (int o = 16; o > 0; o >>= 1) den += __shfl_xor_sync(0xffffffffu, den, o);
    if (den == 0.f) den = 1.f;
    float inv = 1.f / den;

    if (half == 0) {
        int base = warp * 64 + 4 * hl;
        float4 r = *(const float4*)&g_res[base];
        float v0 = r.x + a0 * inv;
        float v1 = r.y + a1 * inv;
        float v2 = r.z + a2 * inv;
        float v3 = r.w + a3 * inv;
        float4 o4;
        o4.x = v0 > 0.f ? v0 : expm1f(v0);
        o4.y = v1 > 0.f ? v1 : expm1f(v1);
        o4.z = v2 > 0.f ? v2 : expm1f(v2);
        o4.w = v3 > 0.f ? v3 : expm1f(v3);
        *(float4*)&out[base] = o4;
    }
}

// ---------------------------------------------------------------------------
extern "C" void kernel_launch(void* const* d_in, const int* in_sizes, int n_in,
                              void* d_out, int out_size) {
    const float* feats = (const float*)d_in[0];
    const float* Wfc   = (const float*)d_in[1];
    const float* Wl    = (const float*)d_in[2];
    const float* Wr    = (const float*)d_in[3];
    const float* Wres  = (const float*)d_in[4];
    const int* esrc    = (const int*)d_in[5];
    const int* edst    = (const int*)d_in[6];
    float* out = (float*)d_out;

    cudaFuncSetAttribute(k_gemm_mma, cudaFuncAttributeMaxDynamicSharedMemorySize, DYN_BYTES);

    k_prep<<<129, 128>>>(Wfc, Wres, Wl, Wr);
    k_gemm_mma<<<NBLK, 256, DYN_BYTES>>>(feats);
    k_rowptr<<<(EE + 255) / 256, 256>>>(edst);
    k_agg<<<(NN * 32 + 255) / 256, 256>>>(esrc, out);
}

// round 14
// speedup vs baseline: 1.0172x; 1.0172x over previous
#include <cuda_runtime.h>
#include <cuda_bf16.h>
#include <cstdint>

#define NN 100000
#define EE 1600000
#define IND 128
#define HID 64
#define MTILE 128
#define NBLK ((NN + MTILE - 1) / MTILE)
#define KCH 64
#define ROWP 68   // padded smem row length (bf16 elems) -> 136B

// scratch (static device globals; allocation-free)
__device__ float g_ft[NN * HID];
__device__ float g_res[NN * HID];
__device__ float g_sdst[NN];
__device__ float g_ssrc[NN];
__device__ int   g_rowptr[NN + 1];
__device__ float g_wl[HID];
__device__ float g_wr[HID];
// B operand [N=128][K=128]: n<64 = W_fc col n, n>=64 = W_res col n-64; hi/lo bf16 split
__device__ __nv_bfloat16 g_Bhi[128 * 128];
__device__ __nv_bfloat16 g_Blo[128 * 128];

// ---------------------------------------------------------------------------
#define MMA_BF16(c, a, b0, b1) \
    asm volatile("mma.sync.aligned.m16n8k16.row.col.f32.bf16.bf16.f32 " \
        "{%0,%1,%2,%3}, {%4,%5,%6,%7}, {%8,%9}, {%0,%1,%2,%3};" \
        : "+f"((c)[0]), "+f"((c)[1]), "+f"((c)[2]), "+f"((c)[3]) \
        : "r"((a)[0]), "r"((a)[1]), "r"((a)[2]), "r"((a)[3]), "r"(b0), "r"(b1))

// ---------------------------------------------------------------------------
// Blocks 0..127: build B operand (transposed, hi/lo bf16 split) B[n][k] = W[k][n].
// Block 128: wl[h] = sum_a W_l[h][a], wr likewise.
__global__ void k_prep(const float* __restrict__ Wfc, const float* __restrict__ Wres,
                       const float* __restrict__ Wl, const float* __restrict__ Wr) {
    if (blockIdx.x == 128) {
        int t = threadIdx.x;
        if (t < 64) {
            float sl = 0.f, sr = 0.f;
#pragma unroll
            for (int a = 0; a < 64; a++) { sl += Wl[t * 64 + a]; sr += Wr[t * 64 + a]; }
            g_wl[t] = sl; g_wr[t] = sr;
        }
        return;
    }
    int n = blockIdx.x;   // 0..127
    int k = threadIdx.x;  // 0..127
    float v = (n < 64) ? Wfc[k * 64 + n] : Wres[k * 64 + (n - 64)];
    __nv_bfloat16 h = __float2bfloat16(v);
    g_Bhi[n * 128 + k] = h;
    g_Blo[n * 128 + k] = __float2bfloat16(v - __bfloat162float(h));
}

// ---------------------------------------------------------------------------
// HMMA fused double GEMM with 3xbf16 split for fp32 accuracy.
// CTA: M=128 x N=128 ([ft|res]) x K=128 in two K=64 chunks. 256 threads = 8 warps.
#define AHI_OFF 0
#define ALO_OFF 17408
#define BHI_OFF 34816
#define BLO_OFF 52224
#define DYN_BYTES 69632
__global__ void __launch_bounds__(256) k_gemm_mma(const float* __restrict__ feats) {
    extern __shared__ __align__(16) char sm[];
    __shared__ float s_wl[64], s_wr[64];
    __nv_bfloat16* Ahi = (__nv_bfloat16*)(sm + AHI_OFF);
    __nv_bfloat16* Alo = (__nv_bfloat16*)(sm + ALO_OFF);
    __nv_bfloat16* Bhi = (__nv_bfloat16*)(sm + BHI_OFF);
    __nv_bfloat16* Blo = (__nv_bfloat16*)(sm + BLO_OFF);

    int tid = threadIdx.x;
    int wid = tid >> 5, lane = tid & 31;
    int g = lane >> 2, t = lane & 3;
    int warpM = wid >> 1, warpN = wid & 1;
    int mbase = warpM * 32, nbase = warpN * 64;
    if (tid < 64) { s_wl[tid] = g_wl[tid]; s_wr[tid] = g_wr[tid]; }

    int m0 = blockIdx.x * MTILE;
    int rowlim = NN - m0;

    float acc[2][8][4];
#pragma unroll
    for (int mt = 0; mt < 2; mt++)
#pragma unroll
        for (int nt = 0; nt < 8; nt++)
#pragma unroll
            for (int q = 0; q < 4; q++) acc[mt][nt][q] = 0.f;

    const uint2* bhig2 = (const uint2*)g_Bhi;  // row = 32 uint2
    const uint2* blog2 = (const uint2*)g_Blo;

    for (int kc = 0; kc < IND; kc += KCH) {
        // ---- A chunk: float4 loads (fp32 -> hi/lo bf16), stored as uint2 ----
#pragma unroll
        for (int i = 0; i < 8; i++) {
            int p = tid + i * 256;      // 0..2047
            int r = p >> 4;             // row 0..127
            int q = p & 15;             // float4 idx in 64-float chunk
            float4 v = (r < rowlim) ? *(const float4*)&feats[(size_t)(m0 + r) * IND + kc + 4 * q]
                                    : make_float4(0.f, 0.f, 0.f, 0.f);
            __nv_bfloat162 h01 = __floats2bfloat162_rn(v.x, v.y);
            __nv_bfloat162 h23 = __floats2bfloat162_rn(v.z, v.w);
            __nv_bfloat162 l01 = __floats2bfloat162_rn(v.x - __bfloat162float(h01.x),
                                                       v.y - __bfloat162float(h01.y));
            __nv_bfloat162 l23 = __floats2bfloat162_rn(v.z - __bfloat162float(h23.x),
                                                       v.w - __bfloat162float(h23.y));
            uint2 hh, ll;
            hh.x = *(uint32_t*)&h01; hh.y = *(uint32_t*)&h23;
            ll.x = *(uint32_t*)&l01; ll.y = *(uint32_t*)&l23;
            *(uint2*)&Ahi[r * ROWP + 4 * q] = hh;
            *(uint2*)&Alo[r * ROWP + 4 * q] = ll;
        }
        // ---- B chunk: uint2 loads (prebuilt bf16 hi/lo) ----
#pragma unroll
        for (int i = 0; i < 8; i++) {
            int p = tid + i * 256;      // 0..2047
            int r = p >> 4;             // row/n 0..127
            int q = p & 15;             // uint2 idx in 32-u32 chunk
            uint2 bh = bhig2[r * 32 + (kc >> 2) + q];
            uint2 bl = blog2[r * 32 + (kc >> 2) + q];
            *(uint2*)&Bhi[r * ROWP + 4 * q] = bh;
            *(uint2*)&Blo[r * ROWP + 4 * q] = bl;
        }
        __syncthreads();

        // ---- mma over 4 k-steps of 16 ----
#pragma unroll
        for (int ks = 0; ks < 4; ks++) {
            int k0 = ks * 16;
            uint32_t aH[2][4], aL[2][4];
#pragma unroll
            for (int mt = 0; mt < 2; mt++) {
                int row = mbase + mt * 16 + g;
                int base = row * ROWP + k0 + 2 * t;
                aH[mt][0] = *(const uint32_t*)&Ahi[base];
                aH[mt][1] = *(const uint32_t*)&Ahi[base + 8 * ROWP];
                aH[mt][2] = *(const uint32_t*)&Ahi[base + 8];
                aH[mt][3] = *(const uint32_t*)&Ahi[base + 8 * ROWP + 8];
                aL[mt][0] = *(const uint32_t*)&Alo[base];
                aL[mt][1] = *(const uint32_t*)&Alo[base + 8 * ROWP];
                aL[mt][2] = *(const uint32_t*)&Alo[base + 8];
                aL[mt][3] = *(const uint32_t*)&Alo[base + 8 * ROWP + 8];
            }
#pragma unroll
            for (int nt = 0; nt < 8; nt++) {
                int n = nbase + nt * 8 + g;
                int bb = n * ROWP + k0 + 2 * t;
                uint32_t bH0 = *(const uint32_t*)&Bhi[bb];
                uint32_t bH1 = *(const uint32_t*)&Bhi[bb + 8];
                uint32_t bL0 = *(const uint32_t*)&Blo[bb];
                uint32_t bL1 = *(const uint32_t*)&Blo[bb + 8];
#pragma unroll
                for (int mt = 0; mt < 2; mt++) {
                    MMA_BF16(acc[mt][nt], aH[mt], bH0, bH1);
                    MMA_BF16(acc[mt][nt], aL[mt], bH0, bH1);
                    MMA_BF16(acc[mt][nt], aH[mt], bL0, bL1);
                }
            }
        }
        __syncthreads();
    }

    // ---- sdst/ssrc from fragments (warps covering cols 0..63 = ft) ----
    if (warpN == 0) {
        float pl[2][2] = {}, pr[2][2] = {};
#pragma unroll
        for (int mt = 0; mt < 2; mt++)
#pragma unroll
            for (int nt = 0; nt < 8; nt++) {
                int col = nt * 8 + 2 * t;
                float wl0 = s_wl[col], wl1 = s_wl[col + 1];
                float wr0 = s_wr[col], wr1 = s_wr[col + 1];
                pl[mt][0] += acc[mt][nt][0] * wl0 + acc[mt][nt][1] * wl1;
                pl[mt][1] += acc[mt][nt][2] * wl0 + acc[mt][nt][3] * wl1;
                pr[mt][0] += acc[mt][nt][0] * wr0 + acc[mt][nt][1] * wr1;
                pr[mt][1] += acc[mt][nt][2] * wr0 + acc[mt][nt][3] * wr1;
            }
#pragma unroll
        for (int off = 1; off <= 2; off <<= 1) {
#pragma unroll
            for (int mt = 0; mt < 2; mt++)
#pragma unroll
                for (int h = 0; h < 2; h++) {
                    pl[mt][h] += __shfl_xor_sync(0xffffffffu, pl[mt][h], off);
                    pr[mt][h] += __shfl_xor_sync(0xffffffffu, pr[mt][h], off);
                }
        }
        if (t == 0) {
#pragma unroll
            for (int mt = 0; mt < 2; mt++)
#pragma unroll
                for (int h = 0; h < 2; h++) {
                    int m = m0 + mbase + mt * 16 + g + h * 8;
                    if (m < NN) { g_sdst[m] = pl[mt][h]; g_ssrc[m] = pr[mt][h]; }
                }
        }
    }

    // ---- stage C in smem, then coalesced copy-out ----
    float* stage = (float*)sm;  // [128][132]
#pragma unroll
    for (int mt = 0; mt < 2; mt++)
#pragma unroll
        for (int nt = 0; nt < 8; nt++) {
            int row = mbase + mt * 16 + g;
            int col = nbase + nt * 8 + 2 * t;
            *(float2*)&stage[row * 132 + col] = make_float2(acc[mt][nt][0], acc[mt][nt][1]);
            *(float2*)&stage[(row + 8) * 132 + col] = make_float2(acc[mt][nt][2], acc[mt][nt][3]);
        }
    __syncthreads();

#pragma unroll
    for (int i = 0; i < 8; i++) {
        int p = tid + i * 256;   // 0..2047
        int r = p >> 4, c4 = p & 15;
        if (r < rowlim) {
            *(float4*)&g_ft[(size_t)(m0 + r) * 64 + c4 * 4]  = *(float4*)&stage[r * 132 + c4 * 4];
            *(float4*)&g_res[(size_t)(m0 + r) * 64 + c4 * 4] = *(float4*)&stage[r * 132 + 64 + c4 * 4];
        }
    }
}

// ---------------------------------------------------------------------------
// CSR row pointers: one load per thread; prev from shfl_up (lane 0 reloads).
__global__ void k_rowptr(const int* __restrict__ dst) {
    int e = blockIdx.x * blockDim.x + threadIdx.x;
    int lane = threadIdx.x & 31;
    int cur = (e < EE) ? dst[e] : 0;
    int prev = __shfl_up_sync(0xffffffffu, cur, 1);
    if (lane == 0) prev = (e == 0) ? -1 : ((e < EE) ? dst[e - 1] : 0);
    if (e < EE) {
        for (int n = prev + 1; n <= cur; n++) g_rowptr[n] = e;
        if (e == EE - 1)
            for (int n = cur + 1; n <= NN; n++) g_rowptr[n] = EE;
    }
}

// ---------------------------------------------------------------------------
// One warp per destination node, single-pass online softmax (R12-proven float2
// gather; __expf fast intrinsics in the hot loop).
__global__ void __launch_bounds__(256) k_agg(const int* __restrict__ src, float* __restrict__ out) {
    int warp = (blockIdx.x * blockDim.x + threadIdx.x) >> 5;
    int lane = threadIdx.x & 31;
    if (warp >= NN) return;

    int s0 = g_rowptr[warp];
    int s1 = g_rowptr[warp + 1];
    float sd = g_sdst[warp];

    float m = -3.402823e38f;
    float acc0 = 0.f, acc1 = 0.f, den = 0.f;
    const float2* __restrict__ ft2 = (const float2*)g_ft;

    for (int e0 = s0; e0 < s1; e0 += 32) {
        int e = e0 + lane;
        float s = -3.402823e38f;
        int sr = 0;
        if (e < s1) {
            sr = src[e];
            s = sd + g_ssrc[sr];
            s = s > 0.f ? s : 0.01f * s;
        }
        float cm = s;
#pragma unroll
        for (int o = 16; o > 0; o >>= 1) cm = fmaxf(cm, __shfl_xor_sync(0xffffffffu, cm, o));
        float newm = fmaxf(m, cm);
        float scale = __expf(m - newm);   // first chunk: exp(-inf)=0, accs are 0 anyway
        acc0 *= scale; acc1 *= scale; den *= scale;
        m = newm;

        float ex = (e < s1) ? __expf(s - m) : 0.f;
        den += ex;
        int cnt = min(32, s1 - e0);
#pragma unroll 4
        for (int j = 0; j < cnt; j++) {
            float exj = __shfl_sync(0xffffffffu, ex, j);
            int srj = __shfl_sync(0xffffffffu, sr, j);
            float2 v = ft2[srj * 32 + lane];
            acc0 += exj * v.x;
            acc1 += exj * v.y;
        }
    }
#pragma unroll
    for (int o = 16; o > 0; o >>= 1) den += __shfl_xor_sync(0xffffffffu, den, o);
    if (den == 0.f) den = 1.f;
    float inv = 1.f / den;

    int base = warp * 64;
    int c0 = 2 * lane, c1 = 2 * lane + 1;
    float v0 = g_res[base + c0] + acc0 * inv;
    float v1 = g_res[base + c1] + acc1 * inv;
    out[base + c0] = v0 > 0.f ? v0 : expm1f(v0);
    out[base + c1] = v1 > 0.f ? v1 : expm1f(v1);
}

// ---------------------------------------------------------------------------
extern "C" void kernel_launch(void* const* d_in, const int* in_sizes, int n_in,
                              void* d_out, int out_size) {
    const float* feats = (const float*)d_in[0];
    const float* Wfc   = (const float*)d_in[1];
    const float* Wl    = (const float*)d_in[2];
    const float* Wr    = (const float*)d_in[3];
    const float* Wres  = (const float*)d_in[4];
    const int* esrc    = (const int*)d_in[5];
    const int* edst    = (const int*)d_in[6];
    float* out = (float*)d_out;

    cudaFuncSetAttribute(k_gemm_mma, cudaFuncAttributeMaxDynamicSharedMemorySize, DYN_BYTES);

    k_prep<<<129, 128>>>(Wfc, Wres, Wl, Wr);
    k_gemm_mma<<<NBLK, 256, DYN_BYTES>>>(feats);
    k_rowptr<<<(EE + 255) / 256, 256>>>(edst);
    k_agg<<<(NN * 32 + 255) / 256, 256>>>(esrc, out);
}

// round 15
// speedup vs baseline: 1.0316x; 1.0142x over previous
#include <cuda_runtime.h>
#include <cuda_bf16.h>
#include <cstdint>

#define NN 100000
#define EE 1600000
#define IND 128
#define HID 64
#define MTILE 128
#define NBLK ((NN + MTILE - 1) / MTILE)
#define KCH 64
#define ROWP 68   // padded smem row length (bf16 elems) -> 136B

// scratch (static device globals; allocation-free)
__device__ float g_ft[NN * HID];
__device__ float g_res[NN * HID];
__device__ float g_sdst[NN];
__device__ float g_ssrc[NN];
__device__ int   g_rowptr[NN + 1];
__device__ float g_wl[HID];
__device__ float g_wr[HID];
// B operand [N=128][K=128]: n<64 = W_fc col n, n>=64 = W_res col n-64; hi/lo bf16 split
__device__ __nv_bfloat16 g_Bhi[128 * 128];
__device__ __nv_bfloat16 g_Blo[128 * 128];

// ---------------------------------------------------------------------------
#define MMA_BF16(c, a, b0, b1) \
    asm volatile("mma.sync.aligned.m16n8k16.row.col.f32.bf16.bf16.f32 " \
        "{%0,%1,%2,%3}, {%4,%5,%6,%7}, {%8,%9}, {%0,%1,%2,%3};" \
        : "+f"((c)[0]), "+f"((c)[1]), "+f"((c)[2]), "+f"((c)[3]) \
        : "r"((a)[0]), "r"((a)[1]), "r"((a)[2]), "r"((a)[3]), "r"(b0), "r"(b1))

// ---------------------------------------------------------------------------
// Blocks 0..127: build B operand (transposed, hi/lo bf16 split) B[n][k] = W[k][n].
// Block 128: wl[h] = sum_a W_l[h][a], wr likewise.
__global__ void k_prep(const float* __restrict__ Wfc, const float* __restrict__ Wres,
                       const float* __restrict__ Wl, const float* __restrict__ Wr) {
    if (blockIdx.x == 128) {
        int t = threadIdx.x;
        if (t < 64) {
            float sl = 0.f, sr = 0.f;
#pragma unroll
            for (int a = 0; a < 64; a++) { sl += Wl[t * 64 + a]; sr += Wr[t * 64 + a]; }
            g_wl[t] = sl; g_wr[t] = sr;
        }
        return;
    }
    int n = blockIdx.x;   // 0..127
    int k = threadIdx.x;  // 0..127
    float v = (n < 64) ? Wfc[k * 64 + n] : Wres[k * 64 + (n - 64)];
    __nv_bfloat16 h = __float2bfloat16(v);
    g_Bhi[n * 128 + k] = h;
    g_Blo[n * 128 + k] = __float2bfloat16(v - __bfloat162float(h));
}

// ---------------------------------------------------------------------------
// HMMA fused double GEMM with 3xbf16 split for fp32 accuracy.
// CTA: M=128 x N=128 ([ft|res]) x K=128 in two K=64 chunks. 256 threads = 8 warps.
#define AHI_OFF 0
#define ALO_OFF 17408
#define BHI_OFF 34816
#define BLO_OFF 52224
#define DYN_BYTES 69632
__global__ void __launch_bounds__(256) k_gemm_mma(const float* __restrict__ feats) {
    extern __shared__ __align__(16) char sm[];
    __shared__ float s_wl[64], s_wr[64];
    __nv_bfloat16* Ahi = (__nv_bfloat16*)(sm + AHI_OFF);
    __nv_bfloat16* Alo = (__nv_bfloat16*)(sm + ALO_OFF);
    __nv_bfloat16* Bhi = (__nv_bfloat16*)(sm + BHI_OFF);
    __nv_bfloat16* Blo = (__nv_bfloat16*)(sm + BLO_OFF);

    int tid = threadIdx.x;
    int wid = tid >> 5, lane = tid & 31;
    int g = lane >> 2, t = lane & 3;
    int warpM = wid >> 1, warpN = wid & 1;
    int mbase = warpM * 32, nbase = warpN * 64;
    if (tid < 64) { s_wl[tid] = g_wl[tid]; s_wr[tid] = g_wr[tid]; }

    int m0 = blockIdx.x * MTILE;
    int rowlim = NN - m0;

    float acc[2][8][4];
#pragma unroll
    for (int mt = 0; mt < 2; mt++)
#pragma unroll
        for (int nt = 0; nt < 8; nt++)
#pragma unroll
            for (int q = 0; q < 4; q++) acc[mt][nt][q] = 0.f;

    const uint2* bhig2 = (const uint2*)g_Bhi;  // row = 32 uint2
    const uint2* blog2 = (const uint2*)g_Blo;

    for (int kc = 0; kc < IND; kc += KCH) {
        // ---- A chunk: float4 loads (fp32 -> hi/lo bf16), stored as uint2 ----
#pragma unroll
        for (int i = 0; i < 8; i++) {
            int p = tid + i * 256;      // 0..2047
            int r = p >> 4;             // row 0..127
            int q = p & 15;             // float4 idx in 64-float chunk
            float4 v = (r < rowlim) ? *(const float4*)&feats[(size_t)(m0 + r) * IND + kc + 4 * q]
                                    : make_float4(0.f, 0.f, 0.f, 0.f);
            __nv_bfloat162 h01 = __floats2bfloat162_rn(v.x, v.y);
            __nv_bfloat162 h23 = __floats2bfloat162_rn(v.z, v.w);
            __nv_bfloat162 l01 = __floats2bfloat162_rn(v.x - __bfloat162float(h01.x),
                                                       v.y - __bfloat162float(h01.y));
            __nv_bfloat162 l23 = __floats2bfloat162_rn(v.z - __bfloat162float(h23.x),
                                                       v.w - __bfloat162float(h23.y));
            uint2 hh, ll;
            hh.x = *(uint32_t*)&h01; hh.y = *(uint32_t*)&h23;
            ll.x = *(uint32_t*)&l01; ll.y = *(uint32_t*)&l23;
            *(uint2*)&Ahi[r * ROWP + 4 * q] = hh;
            *(uint2*)&Alo[r * ROWP + 4 * q] = ll;
        }
        // ---- B chunk: uint2 loads (prebuilt bf16 hi/lo) ----
#pragma unroll
        for (int i = 0; i < 8; i++) {
            int p = tid + i * 256;      // 0..2047
            int r = p >> 4;             // row/n 0..127
            int q = p & 15;             // uint2 idx in 32-u32 chunk
            uint2 bh = bhig2[r * 32 + (kc >> 2) + q];
            uint2 bl = blog2[r * 32 + (kc >> 2) + q];
            *(uint2*)&Bhi[r * ROWP + 4 * q] = bh;
            *(uint2*)&Blo[r * ROWP + 4 * q] = bl;
        }
        __syncthreads();

        // ---- mma over 4 k-steps of 16 ----
#pragma unroll
        for (int ks = 0; ks < 4; ks++) {
            int k0 = ks * 16;
            uint32_t aH[2][4], aL[2][4];
#pragma unroll
            for (int mt = 0; mt < 2; mt++) {
                int row = mbase + mt * 16 + g;
                int base = row * ROWP + k0 + 2 * t;
                aH[mt][0] = *(const uint32_t*)&Ahi[base];
                aH[mt][1] = *(const uint32_t*)&Ahi[base + 8 * ROWP];
                aH[mt][2] = *(const uint32_t*)&Ahi[base + 8];
                aH[mt][3] = *(const uint32_t*)&Ahi[base + 8 * ROWP + 8];
                aL[mt][0] = *(const uint32_t*)&Alo[base];
                aL[mt][1] = *(const uint32_t*)&Alo[base + 8 * ROWP];
                aL[mt][2] = *(const uint32_t*)&Alo[base + 8];
                aL[mt][3] = *(const uint32_t*)&Alo[base + 8 * ROWP + 8];
            }
#pragma unroll
            for (int nt = 0; nt < 8; nt++) {
                int n = nbase + nt * 8 + g;
                int bb = n * ROWP + k0 + 2 * t;
                uint32_t bH0 = *(const uint32_t*)&Bhi[bb];
                uint32_t bH1 = *(const uint32_t*)&Bhi[bb + 8];
                uint32_t bL0 = *(const uint32_t*)&Blo[bb];
                uint32_t bL1 = *(const uint32_t*)&Blo[bb + 8];
#pragma unroll
                for (int mt = 0; mt < 2; mt++) {
                    MMA_BF16(acc[mt][nt], aH[mt], bH0, bH1);
                    MMA_BF16(acc[mt][nt], aL[mt], bH0, bH1);
                    MMA_BF16(acc[mt][nt], aH[mt], bL0, bL1);
                }
            }
        }
        __syncthreads();
    }

    // ---- sdst/ssrc from fragments (warps covering cols 0..63 = ft) ----
    if (warpN == 0) {
        float pl[2][2] = {}, pr[2][2] = {};
#pragma unroll
        for (int mt = 0; mt < 2; mt++)
#pragma unroll
            for (int nt = 0; nt < 8; nt++) {
                int col = nt * 8 + 2 * t;
                float wl0 = s_wl[col], wl1 = s_wl[col + 1];
                float wr0 = s_wr[col], wr1 = s_wr[col + 1];
                pl[mt][0] += acc[mt][nt][0] * wl0 + acc[mt][nt][1] * wl1;
                pl[mt][1] += acc[mt][nt][2] * wl0 + acc[mt][nt][3] * wl1;
                pr[mt][0] += acc[mt][nt][0] * wr0 + acc[mt][nt][1] * wr1;
                pr[mt][1] += acc[mt][nt][2] * wr0 + acc[mt][nt][3] * wr1;
            }
#pragma unroll
        for (int off = 1; off <= 2; off <<= 1) {
#pragma unroll
            for (int mt = 0; mt < 2; mt++)
#pragma unroll
                for (int h = 0; h < 2; h++) {
                    pl[mt][h] += __shfl_xor_sync(0xffffffffu, pl[mt][h], off);
                    pr[mt][h] += __shfl_xor_sync(0xffffffffu, pr[mt][h], off);
                }
        }
        if (t == 0) {
#pragma unroll
            for (int mt = 0; mt < 2; mt++)
#pragma unroll
                for (int h = 0; h < 2; h++) {
                    int m = m0 + mbase + mt * 16 + g + h * 8;
                    if (m < NN) { g_sdst[m] = pl[mt][h]; g_ssrc[m] = pr[mt][h]; }
                }
        }
    }

    // ---- stage C in smem, then coalesced copy-out ----
    float* stage = (float*)sm;  // [128][132]
#pragma unroll
    for (int mt = 0; mt < 2; mt++)
#pragma unroll
        for (int nt = 0; nt < 8; nt++) {
            int row = mbase + mt * 16 + g;
            int col = nbase + nt * 8 + 2 * t;
            *(float2*)&stage[row * 132 + col] = make_float2(acc[mt][nt][0], acc[mt][nt][1]);
            *(float2*)&stage[(row + 8) * 132 + col] = make_float2(acc[mt][nt][2], acc[mt][nt][3]);
        }
    __syncthreads();

#pragma unroll
    for (int i = 0; i < 8; i++) {
        int p = tid + i * 256;   // 0..2047
        int r = p >> 4, c4 = p & 15;
        if (r < rowlim) {
            *(float4*)&g_ft[(size_t)(m0 + r) * 64 + c4 * 4]  = *(float4*)&stage[r * 132 + c4 * 4];
            *(float4*)&g_res[(size_t)(m0 + r) * 64 + c4 * 4] = *(float4*)&stage[r * 132 + 64 + c4 * 4];
        }
    }
}

// ---------------------------------------------------------------------------
// CSR row pointers: one load per thread; prev from shfl_up (lane 0 reloads).
__global__ void k_rowptr(const int* __restrict__ dst) {
    int e = blockIdx.x * blockDim.x + threadIdx.x;
    int lane = threadIdx.x & 31;
    int cur = (e < EE) ? dst[e] : 0;
    int prev = __shfl_up_sync(0xffffffffu, cur, 1);
    if (lane == 0) prev = (e == 0) ? -1 : ((e < EE) ? dst[e - 1] : 0);
    if (e < EE) {
        for (int n = prev + 1; n <= cur; n++) g_rowptr[n] = e;
        if (e == EE - 1)
            for (int n = cur + 1; n <= NN; n++) g_rowptr[n] = EE;
    }
}

// ---------------------------------------------------------------------------
// One HALF-WARP (16 lanes) per destination node — 2 nodes per warp.
// Segmented width-16 shuffles with per-half masks. Single-pass online softmax.
// Gather: each of 16 lanes loads one float4 of the 64-float ft row; byte
// offsets (sr*256) are shuffled so the loop body has no multiply.
__global__ void __launch_bounds__(256) k_agg(const int* __restrict__ src, float* __restrict__ out) {
    int gwarp = (blockIdx.x * blockDim.x + threadIdx.x) >> 5;
    int lane = threadIdx.x & 31;
    int half = lane >> 4;
    int hl = lane & 15;
    int node = gwarp * 2 + half;
    if (node >= NN) return;
    uint32_t hmask = 0xFFFFu << (16 * half);

    int s0 = g_rowptr[node];
    int s1 = g_rowptr[node + 1];
    float sd = g_sdst[node];

    float m = -3.402823e38f;
    float a0 = 0.f, a1 = 0.f, a2 = 0.f, a3 = 0.f, den = 0.f;
    const char* ftb = (const char*)g_ft + hl * 16;   // this lane's float4 slot

    for (int e0 = s0; e0 < s1; e0 += 16) {
        int e = e0 + hl;
        float s = -3.402823e38f;
        int offB = 0;
        if (e < s1) {
            int sr = src[e];
            offB = sr << 8;          // sr * 256 bytes (row stride)
            s = sd + g_ssrc[sr];
            s = s > 0.f ? s : 0.01f * s;
        }
        float cm = s;
#pragma unroll
        for (int o = 8; o > 0; o >>= 1) cm = fmaxf(cm, __shfl_xor_sync(hmask, cm, o, 16));
        float newm = fmaxf(m, cm);
        float scale = __expf(m - newm);   // first chunk: exp(-inf)=0, accs are 0 anyway
        a0 *= scale; a1 *= scale; a2 *= scale; a3 *= scale; den *= scale;
        m = newm;

        float ex = (e < s1) ? __expf(s - m) : 0.f;
        den += ex;
        int cnt = min(16, s1 - e0);
#pragma unroll 4
        for (int j = 0; j < cnt; j++) {
            float exj = __shfl_sync(hmask, ex, j, 16);
            int offj = __shfl_sync(hmask, offB, j, 16);
            float4 v = *(const float4*)(ftb + offj);
            a0 += exj * v.x; a1 += exj * v.y; a2 += exj * v.z; a3 += exj * v.w;
        }
    }
#pragma unroll
    for (int o = 8; o > 0; o >>= 1) den += __shfl_xor_sync(hmask, den, o, 16);
    if (den == 0.f) den = 1.f;
    float inv = 1.f / den;

    int base = node * 64 + 4 * hl;
    float4 r = *(const float4*)&g_res[base];
    float v0 = r.x + a0 * inv;
    float v1 = r.y + a1 * inv;
    float v2 = r.z + a2 * inv;
    float v3 = r.w + a3 * inv;
    float4 o4;
    o4.x = v0 > 0.f ? v0 : expm1f(v0);
    o4.y = v1 > 0.f ? v1 : expm1f(v1);
    o4.z = v2 > 0.f ? v2 : expm1f(v2);
    o4.w = v3 > 0.f ? v3 : expm1f(v3);
    *(float4*)&out[base] = o4;
}

// ---------------------------------------------------------------------------
extern "C" void kernel_launch(void* const* d_in, const int* in_sizes, int n_in,
                              void* d_out, int out_size) {
    const float* feats = (const float*)d_in[0];
    const float* Wfc   = (const float*)d_in[1];
    const float* Wl    = (const float*)d_in[2];
    const float* Wr    = (const float*)d_in[3];
    const float* Wres  = (const float*)d_in[4];
    const int* esrc    = (const int*)d_in[5];
    const int* edst    = (const int*)d_in[6];
    float* out = (float*)d_out;

    cudaFuncSetAttribute(k_gemm_mma, cudaFuncAttributeMaxDynamicSharedMemorySize, DYN_BYTES);

    k_prep<<<129, 128>>>(Wfc, Wres, Wl, Wr);
    k_gemm_mma<<<NBLK, 256, DYN_BYTES>>>(feats);
    k_rowptr<<<(EE + 255) / 256, 256>>>(edst);
    // NN nodes x 16 lanes each = NN*16 threads
    k_agg<<<(NN * 16 + 255) / 256, 256>>>(esrc, out);
}

// round 17
// speedup vs baseline: 1.0490x; 1.0168x over previous
#include <cuda_runtime.h>
#include <cuda_bf16.h>
#include <cstdint>

#define NN 100000
#define EE 1600000
#define IND 128
#define HID 64
#define MTILE 128
#define NBLK ((NN + MTILE - 1) / MTILE)
#define KCH 64
#define ROWP 68   // padded smem row length (bf16 elems) -> 136B

// scratch (static device globals; allocation-free)
__device__ float g_ft[NN * HID];
__device__ float g_res[NN * HID];
__device__ float g_sdst[NN];
__device__ float g_ssrc[NN];
__device__ int   g_rowptr[NN + 1];
__device__ float g_wl[HID];
__device__ float g_wr[HID];
// B operand [N=128][K=128]: n<64 = W_fc col n, n>=64 = W_res col n-64; hi/lo bf16 split
__device__ __nv_bfloat16 g_Bhi[128 * 128];
__device__ __nv_bfloat16 g_Blo[128 * 128];

// ---------------------------------------------------------------------------
#define MMA_BF16(c, a, b0, b1) \
    asm volatile("mma.sync.aligned.m16n8k16.row.col.f32.bf16.bf16.f32 " \
        "{%0,%1,%2,%3}, {%4,%5,%6,%7}, {%8,%9}, {%0,%1,%2,%3};" \
        : "+f"((c)[0]), "+f"((c)[1]), "+f"((c)[2]), "+f"((c)[3]) \
        : "r"((a)[0]), "r"((a)[1]), "r"((a)[2]), "r"((a)[3]), "r"(b0), "r"(b1))

// ---------------------------------------------------------------------------
// Blocks 0..127: build B operand (transposed, hi/lo bf16 split) B[n][k] = W[k][n].
// Block 128: wl[h] = sum_a W_l[h][a], wr likewise.
__global__ void k_prep(const float* __restrict__ Wfc, const float* __restrict__ Wres,
                       const float* __restrict__ Wl, const float* __restrict__ Wr) {
    if (blockIdx.x == 128) {
        int t = threadIdx.x;
        if (t < 64) {
            float sl = 0.f, sr = 0.f;
#pragma unroll
            for (int a = 0; a < 64; a++) { sl += Wl[t * 64 + a]; sr += Wr[t * 64 + a]; }
            g_wl[t] = sl; g_wr[t] = sr;
        }
        return;
    }
    int n = blockIdx.x;   // 0..127
    int k = threadIdx.x;  // 0..127
    float v = (n < 64) ? Wfc[k * 64 + n] : Wres[k * 64 + (n - 64)];
    __nv_bfloat16 h = __float2bfloat16(v);
    g_Bhi[n * 128 + k] = h;
    g_Blo[n * 128 + k] = __float2bfloat16(v - __bfloat162float(h));
}

// ---------------------------------------------------------------------------
// HMMA fused double GEMM with 3xbf16 split for fp32 accuracy.
// CTA: M=128 x N=128 ([ft|res]) x K=128 in two K=64 chunks. 256 threads = 8 warps.
#define AHI_OFF 0
#define ALO_OFF 17408
#define BHI_OFF 34816
#define BLO_OFF 52224
#define DYN_BYTES 69632
__global__ void __launch_bounds__(256) k_gemm_mma(const float* __restrict__ feats) {
    extern __shared__ __align__(16) char sm[];
    __shared__ float s_wl[64], s_wr[64];
    __nv_bfloat16* Ahi = (__nv_bfloat16*)(sm + AHI_OFF);
    __nv_bfloat16* Alo = (__nv_bfloat16*)(sm + ALO_OFF);
    __nv_bfloat16* Bhi = (__nv_bfloat16*)(sm + BHI_OFF);
    __nv_bfloat16* Blo = (__nv_bfloat16*)(sm + BLO_OFF);

    int tid = threadIdx.x;
    int wid = tid >> 5, lane = tid & 31;
    int g = lane >> 2, t = lane & 3;
    int warpM = wid >> 1, warpN = wid & 1;
    int mbase = warpM * 32, nbase = warpN * 64;
    if (tid < 64) { s_wl[tid] = g_wl[tid]; s_wr[tid] = g_wr[tid]; }

    int m0 = blockIdx.x * MTILE;
    int rowlim = NN - m0;

    float acc[2][8][4];
#pragma unroll
    for (int mt = 0; mt < 2; mt++)
#pragma unroll
        for (int nt = 0; nt < 8; nt++)
#pragma unroll
            for (int q = 0; q < 4; q++) acc[mt][nt][q] = 0.f;

    const uint2* bhig2 = (const uint2*)g_Bhi;  // row = 32 uint2
    const uint2* blog2 = (const uint2*)g_Blo;

    for (int kc = 0; kc < IND; kc += KCH) {
        // ---- A chunk: float4 loads (fp32 -> hi/lo bf16), stored as uint2 ----
#pragma unroll
        for (int i = 0; i < 8; i++) {
            int p = tid + i * 256;      // 0..2047
            int r = p >> 4;             // row 0..127
            int q = p & 15;             // float4 idx in 64-float chunk
            float4 v = (r < rowlim) ? *(const float4*)&feats[(size_t)(m0 + r) * IND + kc + 4 * q]
                                    : make_float4(0.f, 0.f, 0.f, 0.f);
            __nv_bfloat162 h01 = __floats2bfloat162_rn(v.x, v.y);
            __nv_bfloat162 h23 = __floats2bfloat162_rn(v.z, v.w);
            __nv_bfloat162 l01 = __floats2bfloat162_rn(v.x - __bfloat162float(h01.x),
                                                       v.y - __bfloat162float(h01.y));
            __nv_bfloat162 l23 = __floats2bfloat162_rn(v.z - __bfloat162float(h23.x),
                                                       v.w - __bfloat162float(h23.y));
            uint2 hh, ll;
            hh.x = *(uint32_t*)&h01; hh.y = *(uint32_t*)&h23;
            ll.x = *(uint32_t*)&l01; ll.y = *(uint32_t*)&l23;
            *(uint2*)&Ahi[r * ROWP + 4 * q] = hh;
            *(uint2*)&Alo[r * ROWP + 4 * q] = ll;
        }
        // ---- B chunk: uint2 loads (prebuilt bf16 hi/lo) ----
#pragma unroll
        for (int i = 0; i < 8; i++) {
            int p = tid + i * 256;      // 0..2047
            int r = p >> 4;             // row/n 0..127
            int q = p & 15;             // uint2 idx in 32-u32 chunk
            uint2 bh = bhig2[r * 32 + (kc >> 2) + q];
            uint2 bl = blog2[r * 32 + (kc >> 2) + q];
            *(uint2*)&Bhi[r * ROWP + 4 * q] = bh;
            *(uint2*)&Blo[r * ROWP + 4 * q] = bl;
        }
        __syncthreads();

        // ---- mma over 4 k-steps of 16 ----
#pragma unroll
        for (int ks = 0; ks < 4; ks++) {
            int k0 = ks * 16;
            uint32_t aH[2][4], aL[2][4];
#pragma unroll
            for (int mt = 0; mt < 2; mt++) {
                int row = mbase + mt * 16 + g;
                int base = row * ROWP + k0 + 2 * t;
                aH[mt][0] = *(const uint32_t*)&Ahi[base];
                aH[mt][1] = *(const uint32_t*)&Ahi[base + 8 * ROWP];
                aH[mt][2] = *(const uint32_t*)&Ahi[base + 8];
                aH[mt][3] = *(const uint32_t*)&Ahi[base + 8 * ROWP + 8];
                aL[mt][0] = *(const uint32_t*)&Alo[base];
                aL[mt][1] = *(const uint32_t*)&Alo[base + 8 * ROWP];
                aL[mt][2] = *(const uint32_t*)&Alo[base + 8];
                aL[mt][3] = *(const uint32_t*)&Alo[base + 8 * ROWP + 8];
            }
#pragma unroll
            for (int nt = 0; nt < 8; nt++) {
                int n = nbase + nt * 8 + g;
                int bb = n * ROWP + k0 + 2 * t;
                uint32_t bH0 = *(const uint32_t*)&Bhi[bb];
                uint32_t bH1 = *(const uint32_t*)&Bhi[bb + 8];
                uint32_t bL0 = *(const uint32_t*)&Blo[bb];
                uint32_t bL1 = *(const uint32_t*)&Blo[bb + 8];
#pragma unroll
                for (int mt = 0; mt < 2; mt++) {
                    MMA_BF16(acc[mt][nt], aH[mt], bH0, bH1);
                    MMA_BF16(acc[mt][nt], aL[mt], bH0, bH1);
                    MMA_BF16(acc[mt][nt], aH[mt], bL0, bL1);
                }
            }
        }
        __syncthreads();
    }

    // ---- sdst/ssrc from fragments (warps covering cols 0..63 = ft) ----
    if (warpN == 0) {
        float pl[2][2] = {}, pr[2][2] = {};
#pragma unroll
        for (int mt = 0; mt < 2; mt++)
#pragma unroll
            for (int nt = 0; nt < 8; nt++) {
                int col = nt * 8 + 2 * t;
                float wl0 = s_wl[col], wl1 = s_wl[col + 1];
                float wr0 = s_wr[col], wr1 = s_wr[col + 1];
                pl[mt][0] += acc[mt][nt][0] * wl0 + acc[mt][nt][1] * wl1;
                pl[mt][1] += acc[mt][nt][2] * wl0 + acc[mt][nt][3] * wl1;
                pr[mt][0] += acc[mt][nt][0] * wr0 + acc[mt][nt][1] * wr1;
                pr[mt][1] += acc[mt][nt][2] * wr0 + acc[mt][nt][3] * wr1;
            }
#pragma unroll
        for (int off = 1; off <= 2; off <<= 1) {
#pragma unroll
            for (int mt = 0; mt < 2; mt++)
#pragma unroll
                for (int h = 0; h < 2; h++) {
                    pl[mt][h] += __shfl_xor_sync(0xffffffffu, pl[mt][h], off);
                    pr[mt][h] += __shfl_xor_sync(0xffffffffu, pr[mt][h], off);
                }
        }
        if (t == 0) {
#pragma unroll
            for (int mt = 0; mt < 2; mt++)
#pragma unroll
                for (int h = 0; h < 2; h++) {
                    int m = m0 + mbase + mt * 16 + g + h * 8;
                    if (m < NN) { g_sdst[m] = pl[mt][h]; g_ssrc[m] = pr[mt][h]; }
                }
        }
    }

    // ---- stage C in smem, then coalesced copy-out ----
    float* stage = (float*)sm;  // [128][132]
#pragma unroll
    for (int mt = 0; mt < 2; mt++)
#pragma unroll
        for (int nt = 0; nt < 8; nt++) {
            int row = mbase + mt * 16 + g;
            int col = nbase + nt * 8 + 2 * t;
            *(float2*)&stage[row * 132 + col] = make_float2(acc[mt][nt][0], acc[mt][nt][1]);
            *(float2*)&stage[(row + 8) * 132 + col] = make_float2(acc[mt][nt][2], acc[mt][nt][3]);
        }
    __syncthreads();

#pragma unroll
    for (int i = 0; i < 8; i++) {
        int p = tid + i * 256;   // 0..2047
        int r = p >> 4, c4 = p & 15;
        if (r < rowlim) {
            *(float4*)&g_ft[(size_t)(m0 + r) * 64 + c4 * 4]  = *(float4*)&stage[r * 132 + c4 * 4];
            *(float4*)&g_res[(size_t)(m0 + r) * 64 + c4 * 4] = *(float4*)&stage[r * 132 + 64 + c4 * 4];
        }
    }
}

// ---------------------------------------------------------------------------
// CSR row pointers: one load per thread; prev from shfl_up (lane 0 reloads).
__global__ void k_rowptr(const int* __restrict__ dst) {
    int e = blockIdx.x * blockDim.x + threadIdx.x;
    int lane = threadIdx.x & 31;
    int cur = (e < EE) ? dst[e] : 0;
    int prev = __shfl_up_sync(0xffffffffu, cur, 1);
    if (lane == 0) prev = (e == 0) ? -1 : ((e < EE) ? dst[e - 1] : 0);
    if (e < EE) {
        for (int n = prev + 1; n <= cur; n++) g_rowptr[n] = e;
        if (e == EE - 1)
            for (int n = cur + 1; n <= NN; n++) g_rowptr[n] = EE;
    }
}

// ---------------------------------------------------------------------------
// One HALF-WARP (16 lanes) per destination node — 2 nodes per warp.
// Segmented width-16 shuffles with per-half masks. Single-pass online softmax.
// Gather: FIXED 16-iteration fully-unrolled loop — phantom edge slots carry
// ex=0 / offB=0 (safe address, zero contribution), so no dynamic trip count:
// 16 independent LDG.128s issue back-to-back for max MLP.
__global__ void __launch_bounds__(256) k_agg(const int* __restrict__ src, float* __restrict__ out) {
    int gwarp = (blockIdx.x * blockDim.x + threadIdx.x) >> 5;
    int lane = threadIdx.x & 31;
    int half = lane >> 4;
    int hl = lane & 15;
    int node = gwarp * 2 + half;
    if (node >= NN) return;
    uint32_t hmask = 0xFFFFu << (16 * half);

    int s0 = g_rowptr[node];
    int s1 = g_rowptr[node + 1];
    float sd = g_sdst[node];

    float m = -3.402823e38f;
    float a0 = 0.f, a1 = 0.f, a2 = 0.f, a3 = 0.f, den = 0.f;
    const char* ftb = (const char*)g_ft + hl * 16;   // this lane's float4 slot

    for (int e0 = s0; e0 < s1; e0 += 16) {
        int e = e0 + hl;
        float s = -3.402823e38f;
        int offB = 0;
        if (e < s1) {
            int sr = src[e];
            offB = sr << 8;          // sr * 256 bytes (row stride)
            s = sd + g_ssrc[sr];
            s = s > 0.f ? s : 0.01f * s;
        }
        float cm = s;
#pragma unroll
        for (int o = 8; o > 0; o >>= 1) cm = fmaxf(cm, __shfl_xor_sync(hmask, cm, o, 16));
        float newm = fmaxf(m, cm);
        float scale = __expf(m - newm);   // first chunk: exp(-inf)=0, accs are 0 anyway
        a0 *= scale; a1 *= scale; a2 *= scale; a3 *= scale; den *= scale;
        m = newm;

        float ex = (e < s1) ? __expf(s - m) : 0.f;
        den += ex;
#pragma unroll
        for (int j = 0; j < 16; j++) {
            float exj = __shfl_sync(hmask, ex, j, 16);
            int offj = __shfl_sync(hmask, offB, j, 16);
            float4 v = *(const float4*)(ftb + offj);
            a0 += exj * v.x; a1 += exj * v.y; a2 += exj * v.z; a3 += exj * v.w;
        }
    }
#pragma unroll
    for (int o = 8; o > 0; o >>= 1) den += __shfl_xor_sync(hmask, den, o, 16);
    if (den == 0.f) den = 1.f;
    float inv = 1.f / den;

    int base = node * 64 + 4 * hl;
    float4 r = *(const float4*)&g_res[base];
    float v0 = r.x + a0 * inv;
    float v1 = r.y + a1 * inv;
    float v2 = r.z + a2 * inv;
    float v3 = r.w + a3 * inv;
    float4 o4;
    o4.x = v0 > 0.f ? v0 : expm1f(v0);
    o4.y = v1 > 0.f ? v1 : expm1f(v1);
    o4.z = v2 > 0.f ? v2 : expm1f(v2);
    o4.w = v3 > 0.f ? v3 : expm1f(v3);
    *(float4*)&out[base] = o4;
}

// ---------------------------------------------------------------------------
extern "C" void kernel_launch(void* const* d_in, const int* in_sizes, int n_in,
                              void* d_out, int out_size) {
    const float* feats = (const float*)d_in[0];
    const float* Wfc   = (const float*)d_in[1];
    const float* Wl    = (const float*)d_in[2];
    const float* Wr    = (const float*)d_in[3];
    const float* Wres  = (const float*)d_in[4];
    const int* esrc    = (const int*)d_in[5];
    const int* edst    = (const int*)d_in[6];
    float* out = (float*)d_out;

    cudaFuncSetAttribute(k_gemm_mma, cudaFuncAttributeMaxDynamicSharedMemorySize, DYN_BYTES);

    k_prep<<<129, 128>>>(Wfc, Wres, Wl, Wr);
    k_gemm_mma<<<NBLK, 256, DYN_BYTES>>>(feats);
    k_rowptr<<<(EE + 255) / 256, 256>>>(edst);
    // NN nodes x 16 lanes each = NN*16 threads
    k_agg<<<(NN * 16 + 255) / 256, 256>>>(esrc, out);
}